// round 4
// baseline (speedup 1.0000x reference)
#include <cuda_runtime.h>
#include <cuda_bf16.h>
#include <cstdint>

// Problem constants (fixed by the dataset)
#define NN   50000
#define EE   800000
#define C    128
#define COUT 64
#define EPSV 1e-5f
#define APITCH 132

// ---------------- device scratch (no allocations allowed) ----------------
// NOTE: g_cnt and g_deg must be ZERO at the start of every kernel_launch call.
// CUDA zero-initializes device globals at load; zero_kernel at the end of each
// call restores the invariant for the next graph replay.
__device__ float g_deg[NN];          // sum of incoming edge weights, then dis = rsqrt(deg+1)
__device__ int   g_cnt[NN];          // incoming-edge counts
__device__ int   g_rowstart[NN + 1]; // CSR row offsets (by dst)
__device__ int   g_cursor[NN];       // fill cursors
__device__ int   g_col[EE];          // CSR col = src node
__device__ float g_wv[EE];           // CSR edge norm weight
__device__ float g_bufA[(size_t)NN * C];
__device__ float g_bufB[(size_t)NN * C];
__device__ float g_bnA[3 * C];       // per-channel scale (BN folded)
__device__ float g_bnB[3 * C];       // per-channel shift (bias+BN folded)
__device__ float g_wt[5 * 128 * 128]; // transposed weights WT[n][k], tf32-rounded

__device__ __forceinline__ float to_tf32(float f) {
    uint32_t u;
    asm("cvt.rna.tf32.f32 %0, %1;" : "=r"(u) : "f"(f));
    return __uint_as_float(u);
}

__device__ __forceinline__ void mma8(float* d, const uint32_t* a, const uint32_t* b) {
    asm volatile(
        "mma.sync.aligned.m16n8k8.row.col.f32.tf32.tf32.f32 "
        "{%0,%1,%2,%3}, {%4,%5,%6,%7}, {%8,%9}, {%0,%1,%2,%3};"
        : "+f"(d[0]), "+f"(d[1]), "+f"(d[2]), "+f"(d[3])
        : "r"(a[0]), "r"(a[1]), "r"(a[2]), "r"(a[3]), "r"(b[0]), "r"(b[1]));
}

// ---------------- kernel 0: edge count/degree atomics + weight transpose ----------------
__global__ void count_tr_kernel(const int* __restrict__ dst, const float* __restrict__ ew, int e,
                                const float* __restrict__ w1, const float* __restrict__ conv_ws,
                                const float* __restrict__ lin1_w, const float* __restrict__ lin2_w) {
    int nb_e = (e + 255) / 256;
    if ((int)blockIdx.x < nb_e) {
        int i = blockIdx.x * 256 + threadIdx.x;
        if (i < e) {
            int d = dst[i];
            atomicAdd(&g_cnt[d], 1);
            atomicAdd(&g_deg[d], ew[i]);
        }
        return;
    }
    int g = (blockIdx.x - nb_e) * 256 + threadIdx.x;
    if (g < 4 * 16384) {
        int mat = g >> 14, idx = g & 16383;
        int k = idx >> 7, nn = idx & 127;
        const float* W = (mat == 0) ? w1 : ((mat == 3) ? lin1_w : (conv_ws + (mat - 1) * 16384));
        g_wt[mat * 16384 + nn * 128 + k] = to_tf32(W[k * 128 + nn]);
    } else if (g < 4 * 16384 + 8192) {
        int idx = g - 4 * 16384;
        int k = idx >> 6, nn = idx & 63;
        g_wt[4 * 16384 + nn * 128 + k] = to_tf32(lin2_w[k * 64 + nn]);
    }
}

// ---------------- kernel 1: single-block scan + dis + cursor + BN fold ----------------
__global__ void scan_fused_kernel(int n, const float* b1,
                                  const float* g1, const float* be1, const float* m1, const float* v1,
                                  const float* conv_bs,
                                  const float* gs, const float* bes, const float* ms, const float* vs) {
    __shared__ int wsum[32];
    __shared__ int carry;
    int t = threadIdx.x, lane = t & 31, w = t >> 5;
    if (t == 0) carry = 0;
    __syncthreads();
    for (int base = 0; base < n; base += 1024) {
        int i = base + t;
        int v = (i < n) ? g_cnt[i] : 0;
        int x = v;
        #pragma unroll
        for (int o = 1; o < 32; o <<= 1) { int y = __shfl_up_sync(0xffffffffu, x, o); if (lane >= o) x += y; }
        if (lane == 31) wsum[w] = x;
        __syncthreads();
        if (w == 0) {
            int s = wsum[lane];
            #pragma unroll
            for (int o = 1; o < 32; o <<= 1) { int y = __shfl_up_sync(0xffffffffu, s, o); if (lane >= o) s += y; }
            wsum[lane] = s;
        }
        __syncthreads();
        int incl = x + (w > 0 ? wsum[w - 1] : 0) + carry;
        if (i < n) g_rowstart[i] = incl - v;
        __syncthreads();
        if (t == 1023) carry = incl;
        __syncthreads();
    }
    if (t == 0) g_rowstart[n] = carry;
    __syncthreads();
    // dis = rsqrt(deg + 1 [self loop]); cursor = rowstart
    for (int i = t; i < n; i += 1024) {
        g_deg[i] = rsqrtf(g_deg[i] + 1.0f);
        g_cursor[i] = g_rowstart[i];
    }
    // BN fold
    if (t < C) {
        int c = t;
        float sc = g1[c] * rsqrtf(v1[c] + EPSV);
        g_bnA[c] = sc;
        g_bnB[c] = be1[c] + (b1[c] - m1[c]) * sc;
        #pragma unroll
        for (int l = 0; l < 2; l++) {
            float s2 = gs[l * C + c] * rsqrtf(vs[l * C + c] + EPSV);
            g_bnA[(1 + l) * C + c] = s2;
            g_bnB[(1 + l) * C + c] = bes[l * C + c] + (conv_bs[l * C + c] - ms[l * C + c]) * s2;
        }
    }
}

// ---------------- kernel 2: CSR fill ----------------
__global__ void fill_kernel(const int* __restrict__ src, const int* __restrict__ dst,
                            const float* __restrict__ ew, int e) {
    int i = blockIdx.x * blockDim.x + threadIdx.x;
    if (i < e) {
        int s = src[i], d = dst[i];
        int pos = atomicAdd(&g_cursor[d], 1);
        g_col[pos] = s;
        g_wv[pos]  = g_deg[s] * ew[i] * g_deg[d];
    }
}

// ---------------- trailing kernel: restore zero invariant for next call ----------------
__global__ void zero_kernel(int n) {
    int i = blockIdx.x * blockDim.x + threadIdx.x;
    if (i < n) { g_cnt[i] = 0; g_deg[i] = 0.0f; }
}

// ---------------- fused layer: out = lrelu( bn( agg(H) @ W ) [+ H] ) ----------------
// 256 threads = 8 warps. Prologue: warp-per-row aggregation of 128 rows into SMEM A
// (tf32). Then m16n8k8 tf32 MMA vs pre-transposed weights, BN+residual+lrelu epilogue.
template <int HASRES>
__global__ __launch_bounds__(256) void agg_gemm_kernel(const float* __restrict__ H,
                                                       const float* __restrict__ WT,
                                                       int layer, float* __restrict__ out, int M) {
    extern __shared__ float sm[];
    float* As = sm;                    // [128][APITCH]
    float* Ws = sm + 128 * APITCH;     // [128][APITCH]

    int tid = threadIdx.x;
    int wid = tid >> 5, lane = tid & 31;
    int m0 = blockIdx.x * 128;

    // stage W
    #pragma unroll
    for (int it = 0; it < 16; it++) {
        int idx = tid + it * 256;
        int r = idx >> 5, q = idx & 31;
        float4 v = *reinterpret_cast<const float4*>(&WT[(size_t)r * 128 + q * 4]);
        *reinterpret_cast<float4*>(&Ws[r * APITCH + q * 4]) = v;
    }

    // aggregation prologue: warp handles rows [wid*16, wid*16+16)
    #pragma unroll 1
    for (int rr = 0; rr < 16; rr++) {
        int r = wid * 16 + rr;
        int m = m0 + r;
        float4 acc = make_float4(0.f, 0.f, 0.f, 0.f);
        if (m < M) {
            float dis = g_deg[m];
            float w0 = dis * dis;
            float4 h4 = *reinterpret_cast<const float4*>(&H[(size_t)m * 128 + lane * 4]);
            acc.x = w0 * h4.x; acc.y = w0 * h4.y; acc.z = w0 * h4.z; acc.w = w0 * h4.w;
            int s = g_rowstart[m], e = g_rowstart[m + 1];
            int k = s;
            for (; k + 8 <= e; k += 8) {
                int   c0 = __ldg(&g_col[k]),     c1 = __ldg(&g_col[k + 1]);
                int   c2 = __ldg(&g_col[k + 2]), c3 = __ldg(&g_col[k + 3]);
                int   c4 = __ldg(&g_col[k + 4]), c5 = __ldg(&g_col[k + 5]);
                int   c6 = __ldg(&g_col[k + 6]), c7 = __ldg(&g_col[k + 7]);
                float w0e = __ldg(&g_wv[k]),     w1e = __ldg(&g_wv[k + 1]);
                float w2e = __ldg(&g_wv[k + 2]), w3e = __ldg(&g_wv[k + 3]);
                float w4e = __ldg(&g_wv[k + 4]), w5e = __ldg(&g_wv[k + 5]);
                float w6e = __ldg(&g_wv[k + 6]), w7e = __ldg(&g_wv[k + 7]);
                float4 v0 = *reinterpret_cast<const float4*>(&H[(size_t)c0 * 128 + lane * 4]);
                float4 v1 = *reinterpret_cast<const float4*>(&H[(size_t)c1 * 128 + lane * 4]);
                float4 v2 = *reinterpret_cast<const float4*>(&H[(size_t)c2 * 128 + lane * 4]);
                float4 v3 = *reinterpret_cast<const float4*>(&H[(size_t)c3 * 128 + lane * 4]);
                float4 v4 = *reinterpret_cast<const float4*>(&H[(size_t)c4 * 128 + lane * 4]);
                float4 v5 = *reinterpret_cast<const float4*>(&H[(size_t)c5 * 128 + lane * 4]);
                float4 v6 = *reinterpret_cast<const float4*>(&H[(size_t)c6 * 128 + lane * 4]);
                float4 v7 = *reinterpret_cast<const float4*>(&H[(size_t)c7 * 128 + lane * 4]);
                acc.x += w0e * v0.x + w1e * v1.x + w2e * v2.x + w3e * v3.x
                       + w4e * v4.x + w5e * v5.x + w6e * v6.x + w7e * v7.x;
                acc.y += w0e * v0.y + w1e * v1.y + w2e * v2.y + w3e * v3.y
                       + w4e * v4.y + w5e * v5.y + w6e * v6.y + w7e * v7.y;
                acc.z += w0e * v0.z + w1e * v1.z + w2e * v2.z + w3e * v3.z
                       + w4e * v4.z + w5e * v5.z + w6e * v6.z + w7e * v7.z;
                acc.w += w0e * v0.w + w1e * v1.w + w2e * v2.w + w3e * v3.w
                       + w4e * v4.w + w5e * v5.w + w6e * v6.w + w7e * v7.w;
            }
            for (; k < e; k++) {
                int cc = __ldg(&g_col[k]);
                float we = __ldg(&g_wv[k]);
                float4 v = *reinterpret_cast<const float4*>(&H[(size_t)cc * 128 + lane * 4]);
                acc.x += we * v.x; acc.y += we * v.y; acc.z += we * v.z; acc.w += we * v.w;
            }
        }
        float* p = &As[r * APITCH + lane * 4];
        p[0] = to_tf32(acc.x); p[1] = to_tf32(acc.y);
        p[2] = to_tf32(acc.z); p[3] = to_tf32(acc.w);
    }
    __syncthreads();

    // MMA: 8 warps as 4(M) x 2(N); warp tile 32 x 64
    int wm = wid & 3, wn = wid >> 2;
    int grp = lane >> 2, tg = lane & 3;
    int arow = wm * 32 + grp;
    int brow = wn * 64 + grp;

    float d[2][8][4];
    #pragma unroll
    for (int i = 0; i < 2; i++)
        #pragma unroll
        for (int j = 0; j < 8; j++)
            #pragma unroll
            for (int q = 0; q < 4; q++) d[i][j][q] = 0.0f;

    #pragma unroll
    for (int k0 = 0; k0 < 16; k0++) {
        int kk = k0 * 8 + tg;
        uint32_t a[2][4];
        #pragma unroll
        for (int mf = 0; mf < 2; mf++) {
            const float* ap = &As[(arow + mf * 16) * APITCH + kk];
            a[mf][0] = __float_as_uint(ap[0]);
            a[mf][2] = __float_as_uint(ap[4]);
            a[mf][1] = __float_as_uint(ap[8 * APITCH]);
            a[mf][3] = __float_as_uint(ap[8 * APITCH + 4]);
        }
        uint32_t b[8][2];
        #pragma unroll
        for (int nf = 0; nf < 8; nf++) {
            const float* bp = &Ws[(brow + nf * 8) * APITCH + kk];
            b[nf][0] = __float_as_uint(bp[0]);
            b[nf][1] = __float_as_uint(bp[4]);
        }
        #pragma unroll
        for (int mf = 0; mf < 2; mf++)
            #pragma unroll
            for (int nf = 0; nf < 8; nf++)
                mma8(d[mf][nf], a[mf], b[nf]);
    }

    // epilogue: BN + residual + lrelu
    const float* bnA = &g_bnA[layer * C];
    const float* bnB = &g_bnB[layer * C];
    #pragma unroll
    for (int mf = 0; mf < 2; mf++) {
        #pragma unroll
        for (int half = 0; half < 2; half++) {
            int m = m0 + wm * 32 + mf * 16 + half * 8 + grp;
            if (m < M) {
                #pragma unroll
                for (int nf = 0; nf < 8; nf++) {
                    int ncol = wn * 64 + nf * 8 + tg * 2;
                    float2 v;
                    v.x = d[mf][nf][half * 2 + 0] * bnA[ncol]     + bnB[ncol];
                    v.y = d[mf][nf][half * 2 + 1] * bnA[ncol + 1] + bnB[ncol + 1];
                    if (HASRES) {
                        float2 rv = *reinterpret_cast<const float2*>(&H[(size_t)m * 128 + ncol]);
                        v.x += rv.x; v.y += rv.y;
                    }
                    v.x = v.x > 0.f ? v.x : 0.01f * v.x;
                    v.y = v.y > 0.f ? v.y : 0.01f * v.y;
                    *reinterpret_cast<float2*>(&out[(size_t)m * 128 + ncol]) = v;
                }
            }
        }
    }
}

// ---------------- fused head: out = lrelu(H@lin1+b1) @ lin2 + b2 ----------------
__global__ __launch_bounds__(256) void head_kernel(const float* __restrict__ H,
                                                   const float* __restrict__ WT1,
                                                   const float* __restrict__ bias1,
                                                   const float* __restrict__ WT2,
                                                   const float* __restrict__ bias2,
                                                   float* __restrict__ out, int M) {
    extern __shared__ float sm[];
    float* As  = sm;                          // [128][APITCH]
    float* W1s = sm + 128 * APITCH;           // [128][APITCH]
    float* W2s = sm + 256 * APITCH;           // [64][APITCH]

    int tid = threadIdx.x;
    int wid = tid >> 5, lane = tid & 31;
    int m0 = blockIdx.x * 128;

    // stage A (tf32), W1, W2
    #pragma unroll
    for (int it = 0; it < 16; it++) {
        int idx = tid + it * 256;
        int r = idx >> 5, q = idx & 31;
        int m = m0 + r;
        float4 v = make_float4(0.f, 0.f, 0.f, 0.f);
        if (m < M) v = *reinterpret_cast<const float4*>(&H[(size_t)m * 128 + q * 4]);
        float* p = &As[r * APITCH + q * 4];
        p[0] = to_tf32(v.x); p[1] = to_tf32(v.y); p[2] = to_tf32(v.z); p[3] = to_tf32(v.w);
    }
    #pragma unroll
    for (int it = 0; it < 16; it++) {
        int idx = tid + it * 256;
        int r = idx >> 5, q = idx & 31;
        float4 v = *reinterpret_cast<const float4*>(&WT1[(size_t)r * 128 + q * 4]);
        *reinterpret_cast<float4*>(&W1s[r * APITCH + q * 4]) = v;
    }
    #pragma unroll
    for (int it = 0; it < 8; it++) {
        int idx = tid + it * 256;
        int r = idx >> 5, q = idx & 31;
        float4 v = *reinterpret_cast<const float4*>(&WT2[(size_t)r * 128 + q * 4]);
        *reinterpret_cast<float4*>(&W2s[r * APITCH + q * 4]) = v;
    }
    __syncthreads();

    int wm = wid & 3, wn = wid >> 2;
    int grp = lane >> 2, tg = lane & 3;
    int arow = wm * 32 + grp;

    // ---- MMA1: z = H @ lin1 (128 x 128) ----
    {
        int brow = wn * 64 + grp;
        float d[2][8][4];
        #pragma unroll
        for (int i = 0; i < 2; i++)
            #pragma unroll
            for (int j = 0; j < 8; j++)
                #pragma unroll
                for (int q = 0; q < 4; q++) d[i][j][q] = 0.0f;

        #pragma unroll
        for (int k0 = 0; k0 < 16; k0++) {
            int kk = k0 * 8 + tg;
            uint32_t a[2][4];
            #pragma unroll
            for (int mf = 0; mf < 2; mf++) {
                const float* ap = &As[(arow + mf * 16) * APITCH + kk];
                a[mf][0] = __float_as_uint(ap[0]);
                a[mf][2] = __float_as_uint(ap[4]);
                a[mf][1] = __float_as_uint(ap[8 * APITCH]);
                a[mf][3] = __float_as_uint(ap[8 * APITCH + 4]);
            }
            uint32_t b[8][2];
            #pragma unroll
            for (int nf = 0; nf < 8; nf++) {
                const float* bp = &W1s[(brow + nf * 8) * APITCH + kk];
                b[nf][0] = __float_as_uint(bp[0]);
                b[nf][1] = __float_as_uint(bp[4]);
            }
            #pragma unroll
            for (int mf = 0; mf < 2; mf++)
                #pragma unroll
                for (int nf = 0; nf < 8; nf++)
                    mma8(d[mf][nf], a[mf], b[nf]);
        }
        __syncthreads();   // everyone done reading As before overwrite

        // write lrelu(z + bias1) back into As (tf32) for MMA2
        #pragma unroll
        for (int mf = 0; mf < 2; mf++) {
            #pragma unroll
            for (int half = 0; half < 2; half++) {
                int r = wm * 32 + mf * 16 + half * 8 + grp;
                #pragma unroll
                for (int nf = 0; nf < 8; nf++) {
                    int ncol = wn * 64 + nf * 8 + tg * 2;
                    float vx = d[mf][nf][half * 2 + 0] + bias1[ncol];
                    float vy = d[mf][nf][half * 2 + 1] + bias1[ncol + 1];
                    vx = vx > 0.f ? vx : 0.01f * vx;
                    vy = vy > 0.f ? vy : 0.01f * vy;
                    As[r * APITCH + ncol]     = to_tf32(vx);
                    As[r * APITCH + ncol + 1] = to_tf32(vy);
                }
            }
        }
        __syncthreads();
    }

    // ---- MMA2: out = z @ lin2 (128 x 64) ----
    {
        int brow = wn * 32 + grp;
        float d[2][4][4];
        #pragma unroll
        for (int i = 0; i < 2; i++)
            #pragma unroll
            for (int j = 0; j < 4; j++)
                #pragma unroll
                for (int q = 0; q < 4; q++) d[i][j][q] = 0.0f;

        #pragma unroll
        for (int k0 = 0; k0 < 16; k0++) {
            int kk = k0 * 8 + tg;
            uint32_t a[2][4];
            #pragma unroll
            for (int mf = 0; mf < 2; mf++) {
                const float* ap = &As[(arow + mf * 16) * APITCH + kk];
                a[mf][0] = __float_as_uint(ap[0]);
                a[mf][2] = __float_as_uint(ap[4]);
                a[mf][1] = __float_as_uint(ap[8 * APITCH]);
                a[mf][3] = __float_as_uint(ap[8 * APITCH + 4]);
            }
            uint32_t b[4][2];
            #pragma unroll
            for (int nf = 0; nf < 4; nf++) {
                const float* bp = &W2s[(brow + nf * 8) * APITCH + kk];
                b[nf][0] = __float_as_uint(bp[0]);
                b[nf][1] = __float_as_uint(bp[4]);
            }
            #pragma unroll
            for (int mf = 0; mf < 2; mf++)
                #pragma unroll
                for (int nf = 0; nf < 4; nf++)
                    mma8(d[mf][nf], a[mf], b[nf]);
        }

        #pragma unroll
        for (int mf = 0; mf < 2; mf++) {
            #pragma unroll
            for (int half = 0; half < 2; half++) {
                int m = m0 + wm * 32 + mf * 16 + half * 8 + grp;
                if (m < M) {
                    #pragma unroll
                    for (int nf = 0; nf < 4; nf++) {
                        int ncol = wn * 32 + nf * 8 + tg * 2;
                        float2 v;
                        v.x = d[mf][nf][half * 2 + 0] + bias2[ncol];
                        v.y = d[mf][nf][half * 2 + 1] + bias2[ncol + 1];
                        *reinterpret_cast<float2*>(&out[(size_t)m * COUT + ncol]) = v;
                    }
                }
            }
        }
    }
}

// ---------------- launch ----------------
extern "C" void kernel_launch(void* const* d_in, const int* in_sizes, int n_in,
                              void* d_out, int out_size) {
    const float* x       = (const float*)d_in[0];
    const int*   ei      = (const int*)d_in[1];
    const float* ew      = (const float*)d_in[2];
    const float* w1      = (const float*)d_in[3];
    const float* b1      = (const float*)d_in[4];
    const float* bn1_g   = (const float*)d_in[5];
    const float* bn1_b   = (const float*)d_in[6];
    const float* bn1_m   = (const float*)d_in[7];
    const float* bn1_v   = (const float*)d_in[8];
    const float* conv_ws = (const float*)d_in[9];
    const float* conv_bs = (const float*)d_in[10];
    const float* bns_g   = (const float*)d_in[11];
    const float* bns_b   = (const float*)d_in[12];
    const float* bns_m   = (const float*)d_in[13];
    const float* bns_v   = (const float*)d_in[14];
    const float* lin1_w  = (const float*)d_in[15];
    const float* lin1_b  = (const float*)d_in[16];
    const float* lin2_w  = (const float*)d_in[17];
    const float* lin2_b  = (const float*)d_in[18];

    int n = in_sizes[0] / C;     // 50000
    int e = in_sizes[2];         // 800000
    const int* srcp = ei;
    const int* dstp = ei + e;

    const int SMEM_LAYER = 256 * APITCH * 4;   // 135168
    const int SMEM_HEAD  = 320 * APITCH * 4;   // 168960

    cudaFuncSetAttribute(agg_gemm_kernel<0>, cudaFuncAttributeMaxDynamicSharedMemorySize, SMEM_LAYER);
    cudaFuncSetAttribute(agg_gemm_kernel<1>, cudaFuncAttributeMaxDynamicSharedMemorySize, SMEM_LAYER);
    cudaFuncSetAttribute(head_kernel,        cudaFuncAttributeMaxDynamicSharedMemorySize, SMEM_HEAD);

    float* wt = nullptr;
    cudaGetSymbolAddress((void**)&wt, g_wt);
    float* bufA = nullptr;
    cudaGetSymbolAddress((void**)&bufA, g_bufA);
    float* bufB = nullptr;
    cudaGetSymbolAddress((void**)&bufB, g_bufB);

    // setup: 3 kernels (g_cnt/g_deg arrive zeroed from previous call / load init)
    int nb_e = (e + 255) / 256;
    count_tr_kernel<<<nb_e + (5 * 16384 - 8192 + 255) / 256, 256>>>(dstp, ew, e, w1, conv_ws, lin1_w, lin2_w);
    scan_fused_kernel<<<1, 1024>>>(n, b1, bn1_g, bn1_b, bn1_m, bn1_v,
                                   conv_bs, bns_g, bns_b, bns_m, bns_v);
    fill_kernel<<<nb_e, 256>>>(srcp, dstp, ew, e);

    int gblocks = (n + 127) / 128;

    // layer 0: bufA = lrelu(bn0(agg(x) @ w1))         <- ncu capture slot
    agg_gemm_kernel<0><<<gblocks, 256, SMEM_LAYER>>>(x, wt + 0 * 16384, 0, bufA, n);
    // layer 1: bufB = lrelu(bn1(agg(bufA) @ w2) + bufA)
    agg_gemm_kernel<1><<<gblocks, 256, SMEM_LAYER>>>(bufA, wt + 1 * 16384, 1, bufB, n);
    // layer 2: bufA = lrelu(bn2(agg(bufB) @ w3) + bufB)
    agg_gemm_kernel<1><<<gblocks, 256, SMEM_LAYER>>>(bufB, wt + 2 * 16384, 2, bufA, n);
    // heads fused: out = lrelu(bufA @ lin1 + b) @ lin2 + b
    head_kernel<<<gblocks, 256, SMEM_HEAD>>>(bufA, wt + 3 * 16384, lin1_b, wt + 4 * 16384, lin2_b,
                                             (float*)d_out, n);

    // restore zero invariant for next call
    zero_kernel<<<(n + 255) / 256, 256>>>(n);
}

// round 5
// speedup vs baseline: 1.4895x; 1.4895x over previous
#include <cuda_runtime.h>
#include <cuda_bf16.h>
#include <cstdint>

// Problem constants (fixed by the dataset)
#define NN   50000
#define EE   800000
#define C    128
#define COUT 64
#define EPSV 1e-5f
#define APITCH 132

// ---------------- device scratch (no allocations allowed) ----------------
// g_cnt/g_deg must be ZERO at the start of every call; zero_kernel at the end
// restores the invariant (globals are zero-initialized at module load).
__device__ float g_deg[NN];          // sum of incoming edge weights, then dis = rsqrt(deg+1)
__device__ int   g_cnt[NN];          // incoming-edge counts
__device__ int   g_rowstart[NN + 1]; // CSR row offsets (by dst)
__device__ int   g_cursor[NN];       // fill cursors
__device__ int   g_col[EE];          // CSR col = src node
__device__ float g_wv[EE];           // CSR edge norm weight
__device__ float g_agg[(size_t)NN * C];   // aggregation output
__device__ float g_bufA[(size_t)NN * C];
__device__ float g_bufB[(size_t)NN * C];
__device__ float g_bnA[3 * C];       // per-channel scale (BN folded)
__device__ float g_bnB[3 * C];       // per-channel shift (bias+BN folded)
__device__ float g_wt[5 * 128 * 128]; // transposed weights WT[n][k], tf32-rounded

__device__ __forceinline__ float to_tf32(float f) {
    uint32_t u;
    asm("cvt.rna.tf32.f32 %0, %1;" : "=r"(u) : "f"(f));
    return __uint_as_float(u);
}

__device__ __forceinline__ void mma8(float* d, const uint32_t* a, const uint32_t* b) {
    asm volatile(
        "mma.sync.aligned.m16n8k8.row.col.f32.tf32.tf32.f32 "
        "{%0,%1,%2,%3}, {%4,%5,%6,%7}, {%8,%9}, {%0,%1,%2,%3};"
        : "+f"(d[0]), "+f"(d[1]), "+f"(d[2]), "+f"(d[3])
        : "r"(a[0]), "r"(a[1]), "r"(a[2]), "r"(a[3]), "r"(b[0]), "r"(b[1]));
}

// ---------------- kernel 0: edge count/degree atomics + weight transpose ----------------
__global__ void count_tr_kernel(const int* __restrict__ dst, const float* __restrict__ ew, int e,
                                const float* __restrict__ w1, const float* __restrict__ conv_ws,
                                const float* __restrict__ lin1_w, const float* __restrict__ lin2_w) {
    int nb_e = (e + 255) / 256;
    if ((int)blockIdx.x < nb_e) {
        int i = blockIdx.x * 256 + threadIdx.x;
        if (i < e) {
            int d = dst[i];
            atomicAdd(&g_cnt[d], 1);
            atomicAdd(&g_deg[d], ew[i]);
        }
        return;
    }
    int g = (blockIdx.x - nb_e) * 256 + threadIdx.x;
    if (g < 4 * 16384) {
        int mat = g >> 14, idx = g & 16383;
        int k = idx >> 7, nn = idx & 127;
        const float* W = (mat == 0) ? w1 : ((mat == 3) ? lin1_w : (conv_ws + (mat - 1) * 16384));
        g_wt[mat * 16384 + nn * 128 + k] = to_tf32(W[k * 128 + nn]);
    } else if (g < 4 * 16384 + 8192) {
        int idx = g - 4 * 16384;
        int k = idx >> 6, nn = idx & 63;
        g_wt[4 * 16384 + nn * 128 + k] = to_tf32(lin2_w[k * 64 + nn]);
    }
}

// ---------------- kernel 1: single-block scan + dis + cursor + BN fold ----------------
__global__ void scan_fused_kernel(int n, const float* b1,
                                  const float* g1, const float* be1, const float* m1, const float* v1,
                                  const float* conv_bs,
                                  const float* gs, const float* bes, const float* ms, const float* vs) {
    __shared__ int wsum[32];
    __shared__ int carry;
    int t = threadIdx.x, lane = t & 31, w = t >> 5;
    if (t == 0) carry = 0;
    __syncthreads();
    for (int base = 0; base < n; base += 1024) {
        int i = base + t;
        int v = (i < n) ? g_cnt[i] : 0;
        int x = v;
        #pragma unroll
        for (int o = 1; o < 32; o <<= 1) { int y = __shfl_up_sync(0xffffffffu, x, o); if (lane >= o) x += y; }
        if (lane == 31) wsum[w] = x;
        __syncthreads();
        if (w == 0) {
            int s = wsum[lane];
            #pragma unroll
            for (int o = 1; o < 32; o <<= 1) { int y = __shfl_up_sync(0xffffffffu, s, o); if (lane >= o) s += y; }
            wsum[lane] = s;
        }
        __syncthreads();
        int incl = x + (w > 0 ? wsum[w - 1] : 0) + carry;
        if (i < n) g_rowstart[i] = incl - v;
        __syncthreads();
        if (t == 1023) carry = incl;
        __syncthreads();
    }
    if (t == 0) g_rowstart[n] = carry;
    __syncthreads();
    for (int i = t; i < n; i += 1024) {
        g_deg[i] = rsqrtf(g_deg[i] + 1.0f);   // + self loop
        g_cursor[i] = g_rowstart[i];
    }
    if (t < C) {
        int c = t;
        float sc = g1[c] * rsqrtf(v1[c] + EPSV);
        g_bnA[c] = sc;
        g_bnB[c] = be1[c] + (b1[c] - m1[c]) * sc;
        #pragma unroll
        for (int l = 0; l < 2; l++) {
            float s2 = gs[l * C + c] * rsqrtf(vs[l * C + c] + EPSV);
            g_bnA[(1 + l) * C + c] = s2;
            g_bnB[(1 + l) * C + c] = bes[l * C + c] + (conv_bs[l * C + c] - ms[l * C + c]) * s2;
        }
    }
}

// ---------------- kernel 2: CSR fill ----------------
__global__ void fill_kernel(const int* __restrict__ src, const int* __restrict__ dst,
                            const float* __restrict__ ew, int e) {
    int i = blockIdx.x * blockDim.x + threadIdx.x;
    if (i < e) {
        int s = src[i], d = dst[i];
        int pos = atomicAdd(&g_cursor[d], 1);
        g_col[pos] = s;
        g_wv[pos]  = g_deg[s] * ew[i] * g_deg[d];
    }
}

// ---------------- trailing kernel: restore zero invariant ----------------
__global__ void zero_kernel(int n) {
    int i = blockIdx.x * blockDim.x + threadIdx.x;
    if (i < n) { g_cnt[i] = 0; g_deg[i] = 0.0f; }
}

// ---------------- aggregation: g_agg[i] = selfnorm*H[i] + sum_e w_e * H[col_e] ----------------
// warp-per-row, 8 warps per 256-thread block, zero smem -> high occupancy.
__global__ __launch_bounds__(256) void agg_kernel(const float* __restrict__ H, int n) {
    int wid = threadIdx.x >> 5, lane = threadIdx.x & 31;
    int m = blockIdx.x * 8 + wid;
    if (m >= n) return;

    float dis = g_deg[m];
    float w0 = dis * dis;
    float4 h4 = *reinterpret_cast<const float4*>(&H[(size_t)m * 128 + lane * 4]);
    float4 acc = make_float4(w0 * h4.x, w0 * h4.y, w0 * h4.z, w0 * h4.w);

    int s = g_rowstart[m], e = g_rowstart[m + 1];
    int k = s;
    for (; k + 8 <= e; k += 8) {
        int   c0 = __ldg(&g_col[k]),     c1 = __ldg(&g_col[k + 1]);
        int   c2 = __ldg(&g_col[k + 2]), c3 = __ldg(&g_col[k + 3]);
        int   c4 = __ldg(&g_col[k + 4]), c5 = __ldg(&g_col[k + 5]);
        int   c6 = __ldg(&g_col[k + 6]), c7 = __ldg(&g_col[k + 7]);
        float w0e = __ldg(&g_wv[k]),     w1e = __ldg(&g_wv[k + 1]);
        float w2e = __ldg(&g_wv[k + 2]), w3e = __ldg(&g_wv[k + 3]);
        float w4e = __ldg(&g_wv[k + 4]), w5e = __ldg(&g_wv[k + 5]);
        float w6e = __ldg(&g_wv[k + 6]), w7e = __ldg(&g_wv[k + 7]);
        float4 v0 = *reinterpret_cast<const float4*>(&H[(size_t)c0 * 128 + lane * 4]);
        float4 v1 = *reinterpret_cast<const float4*>(&H[(size_t)c1 * 128 + lane * 4]);
        float4 v2 = *reinterpret_cast<const float4*>(&H[(size_t)c2 * 128 + lane * 4]);
        float4 v3 = *reinterpret_cast<const float4*>(&H[(size_t)c3 * 128 + lane * 4]);
        float4 v4 = *reinterpret_cast<const float4*>(&H[(size_t)c4 * 128 + lane * 4]);
        float4 v5 = *reinterpret_cast<const float4*>(&H[(size_t)c5 * 128 + lane * 4]);
        float4 v6 = *reinterpret_cast<const float4*>(&H[(size_t)c6 * 128 + lane * 4]);
        float4 v7 = *reinterpret_cast<const float4*>(&H[(size_t)c7 * 128 + lane * 4]);
        acc.x += w0e * v0.x + w1e * v1.x + w2e * v2.x + w3e * v3.x
               + w4e * v4.x + w5e * v5.x + w6e * v6.x + w7e * v7.x;
        acc.y += w0e * v0.y + w1e * v1.y + w2e * v2.y + w3e * v3.y
               + w4e * v4.y + w5e * v5.y + w6e * v6.y + w7e * v7.y;
        acc.z += w0e * v0.z + w1e * v1.z + w2e * v2.z + w3e * v3.z
               + w4e * v4.z + w5e * v5.z + w6e * v6.z + w7e * v7.z;
        acc.w += w0e * v0.w + w1e * v1.w + w2e * v2.w + w3e * v3.w
               + w4e * v4.w + w5e * v5.w + w6e * v6.w + w7e * v7.w;
    }
    for (; k < e; k++) {
        int cc = __ldg(&g_col[k]);
        float we = __ldg(&g_wv[k]);
        float4 v = *reinterpret_cast<const float4*>(&H[(size_t)cc * 128 + lane * 4]);
        acc.x += we * v.x; acc.y += we * v.y; acc.z += we * v.z; acc.w += we * v.w;
    }
    *reinterpret_cast<float4*>(&g_agg[(size_t)m * 128 + lane * 4]) = acc;
}

// ---------------- GEMM + BN + residual + lrelu: out = lrelu(bn(agg@W) [+ H]) ----------------
template <int HASRES>
__global__ __launch_bounds__(256) void gemm_bn_kernel(const float* __restrict__ WT,
                                                      int layer, const float* __restrict__ H,
                                                      float* __restrict__ out, int M) {
    extern __shared__ float sm[];
    float* As = sm;                    // [128][APITCH]
    float* Ws = sm + 128 * APITCH;     // [128][APITCH]

    int tid = threadIdx.x;
    int wid = tid >> 5, lane = tid & 31;
    int m0 = blockIdx.x * 128;

    // stage A (tf32) from g_agg
    #pragma unroll
    for (int it = 0; it < 16; it++) {
        int idx = tid + it * 256;
        int r = idx >> 5, q = idx & 31;
        int m = m0 + r;
        float4 v = make_float4(0.f, 0.f, 0.f, 0.f);
        if (m < M) v = *reinterpret_cast<const float4*>(&g_agg[(size_t)m * 128 + q * 4]);
        float* p = &As[r * APITCH + q * 4];
        p[0] = to_tf32(v.x); p[1] = to_tf32(v.y); p[2] = to_tf32(v.z); p[3] = to_tf32(v.w);
    }
    // stage W
    #pragma unroll
    for (int it = 0; it < 16; it++) {
        int idx = tid + it * 256;
        int r = idx >> 5, q = idx & 31;
        float4 v = *reinterpret_cast<const float4*>(&WT[(size_t)r * 128 + q * 4]);
        *reinterpret_cast<float4*>(&Ws[r * APITCH + q * 4]) = v;
    }
    __syncthreads();

    int wm = wid & 3, wn = wid >> 2;
    int grp = lane >> 2, tg = lane & 3;
    int arow = wm * 32 + grp;
    int brow = wn * 64 + grp;

    float d[2][8][4];
    #pragma unroll
    for (int i = 0; i < 2; i++)
        #pragma unroll
        for (int j = 0; j < 8; j++)
            #pragma unroll
            for (int q = 0; q < 4; q++) d[i][j][q] = 0.0f;

    #pragma unroll
    for (int k0 = 0; k0 < 16; k0++) {
        int kk = k0 * 8 + tg;
        uint32_t a[2][4];
        #pragma unroll
        for (int mf = 0; mf < 2; mf++) {
            const float* ap = &As[(arow + mf * 16) * APITCH + kk];
            a[mf][0] = __float_as_uint(ap[0]);
            a[mf][2] = __float_as_uint(ap[4]);
            a[mf][1] = __float_as_uint(ap[8 * APITCH]);
            a[mf][3] = __float_as_uint(ap[8 * APITCH + 4]);
        }
        uint32_t b[8][2];
        #pragma unroll
        for (int nf = 0; nf < 8; nf++) {
            const float* bp = &Ws[(brow + nf * 8) * APITCH + kk];
            b[nf][0] = __float_as_uint(bp[0]);
            b[nf][1] = __float_as_uint(bp[4]);
        }
        #pragma unroll
        for (int mf = 0; mf < 2; mf++)
            #pragma unroll
            for (int nf = 0; nf < 8; nf++)
                mma8(d[mf][nf], a[mf], b[nf]);
    }

    const float* bnA = &g_bnA[layer * C];
    const float* bnB = &g_bnB[layer * C];
    #pragma unroll
    for (int mf = 0; mf < 2; mf++) {
        #pragma unroll
        for (int half = 0; half < 2; half++) {
            int m = m0 + wm * 32 + mf * 16 + half * 8 + grp;
            if (m < M) {
                #pragma unroll
                for (int nf = 0; nf < 8; nf++) {
                    int ncol = wn * 64 + nf * 8 + tg * 2;
                    float2 v;
                    v.x = d[mf][nf][half * 2 + 0] * bnA[ncol]     + bnB[ncol];
                    v.y = d[mf][nf][half * 2 + 1] * bnA[ncol + 1] + bnB[ncol + 1];
                    if (HASRES) {
                        float2 rv = *reinterpret_cast<const float2*>(&H[(size_t)m * 128 + ncol]);
                        v.x += rv.x; v.y += rv.y;
                    }
                    v.x = v.x > 0.f ? v.x : 0.01f * v.x;
                    v.y = v.y > 0.f ? v.y : 0.01f * v.y;
                    *reinterpret_cast<float2*>(&out[(size_t)m * 128 + ncol]) = v;
                }
            }
        }
    }
}

// ---------------- fused head: out = lrelu(H@lin1+b1) @ lin2 + b2 ----------------
__global__ __launch_bounds__(256) void head_kernel(const float* __restrict__ H,
                                                   const float* __restrict__ WT1,
                                                   const float* __restrict__ bias1,
                                                   const float* __restrict__ WT2,
                                                   const float* __restrict__ bias2,
                                                   float* __restrict__ out, int M) {
    extern __shared__ float sm[];
    float* As  = sm;                          // [128][APITCH]
    float* W1s = sm + 128 * APITCH;           // [128][APITCH]
    float* W2s = sm + 256 * APITCH;           // [64][APITCH]

    int tid = threadIdx.x;
    int wid = tid >> 5, lane = tid & 31;
    int m0 = blockIdx.x * 128;

    #pragma unroll
    for (int it = 0; it < 16; it++) {
        int idx = tid + it * 256;
        int r = idx >> 5, q = idx & 31;
        int m = m0 + r;
        float4 v = make_float4(0.f, 0.f, 0.f, 0.f);
        if (m < M) v = *reinterpret_cast<const float4*>(&H[(size_t)m * 128 + q * 4]);
        float* p = &As[r * APITCH + q * 4];
        p[0] = to_tf32(v.x); p[1] = to_tf32(v.y); p[2] = to_tf32(v.z); p[3] = to_tf32(v.w);
    }
    #pragma unroll
    for (int it = 0; it < 16; it++) {
        int idx = tid + it * 256;
        int r = idx >> 5, q = idx & 31;
        float4 v = *reinterpret_cast<const float4*>(&WT1[(size_t)r * 128 + q * 4]);
        *reinterpret_cast<float4*>(&W1s[r * APITCH + q * 4]) = v;
    }
    #pragma unroll
    for (int it = 0; it < 8; it++) {
        int idx = tid + it * 256;
        int r = idx >> 5, q = idx & 31;
        float4 v = *reinterpret_cast<const float4*>(&WT2[(size_t)r * 128 + q * 4]);
        *reinterpret_cast<float4*>(&W2s[r * APITCH + q * 4]) = v;
    }
    __syncthreads();

    int wm = wid & 3, wn = wid >> 2;
    int grp = lane >> 2, tg = lane & 3;
    int arow = wm * 32 + grp;

    // ---- MMA1: z = H @ lin1 (128 x 128) ----
    {
        int brow = wn * 64 + grp;
        float d[2][8][4];
        #pragma unroll
        for (int i = 0; i < 2; i++)
            #pragma unroll
            for (int j = 0; j < 8; j++)
                #pragma unroll
                for (int q = 0; q < 4; q++) d[i][j][q] = 0.0f;

        #pragma unroll
        for (int k0 = 0; k0 < 16; k0++) {
            int kk = k0 * 8 + tg;
            uint32_t a[2][4];
            #pragma unroll
            for (int mf = 0; mf < 2; mf++) {
                const float* ap = &As[(arow + mf * 16) * APITCH + kk];
                a[mf][0] = __float_as_uint(ap[0]);
                a[mf][2] = __float_as_uint(ap[4]);
                a[mf][1] = __float_as_uint(ap[8 * APITCH]);
                a[mf][3] = __float_as_uint(ap[8 * APITCH + 4]);
            }
            uint32_t b[8][2];
            #pragma unroll
            for (int nf = 0; nf < 8; nf++) {
                const float* bp = &W1s[(brow + nf * 8) * APITCH + kk];
                b[nf][0] = __float_as_uint(bp[0]);
                b[nf][1] = __float_as_uint(bp[4]);
            }
            #pragma unroll
            for (int mf = 0; mf < 2; mf++)
                #pragma unroll
                for (int nf = 0; nf < 8; nf++)
                    mma8(d[mf][nf], a[mf], b[nf]);
        }
        __syncthreads();

        // write lrelu(z + bias1) back into As (tf32) for MMA2
        #pragma unroll
        for (int mf = 0; mf < 2; mf++) {
            #pragma unroll
            for (int half = 0; half < 2; half++) {
                int r = wm * 32 + mf * 16 + half * 8 + grp;
                #pragma unroll
                for (int nf = 0; nf < 8; nf++) {
                    int ncol = wn * 64 + nf * 8 + tg * 2;
                    float vx = d[mf][nf][half * 2 + 0] + bias1[ncol];
                    float vy = d[mf][nf][half * 2 + 1] + bias1[ncol + 1];
                    vx = vx > 0.f ? vx : 0.01f * vx;
                    vy = vy > 0.f ? vy : 0.01f * vy;
                    As[r * APITCH + ncol]     = to_tf32(vx);
                    As[r * APITCH + ncol + 1] = to_tf32(vy);
                }
            }
        }
        __syncthreads();
    }

    // ---- MMA2: out = z @ lin2 (128 x 64) ----
    {
        int brow = wn * 32 + grp;
        float d[2][4][4];
        #pragma unroll
        for (int i = 0; i < 2; i++)
            #pragma unroll
            for (int j = 0; j < 4; j++)
                #pragma unroll
                for (int q = 0; q < 4; q++) d[i][j][q] = 0.0f;

        #pragma unroll
        for (int k0 = 0; k0 < 16; k0++) {
            int kk = k0 * 8 + tg;
            uint32_t a[2][4];
            #pragma unroll
            for (int mf = 0; mf < 2; mf++) {
                const float* ap = &As[(arow + mf * 16) * APITCH + kk];
                a[mf][0] = __float_as_uint(ap[0]);
                a[mf][2] = __float_as_uint(ap[4]);
                a[mf][1] = __float_as_uint(ap[8 * APITCH]);
                a[mf][3] = __float_as_uint(ap[8 * APITCH + 4]);
            }
            uint32_t b[4][2];
            #pragma unroll
            for (int nf = 0; nf < 4; nf++) {
                const float* bp = &W2s[(brow + nf * 8) * APITCH + kk];
                b[nf][0] = __float_as_uint(bp[0]);
                b[nf][1] = __float_as_uint(bp[4]);
            }
            #pragma unroll
            for (int mf = 0; mf < 2; mf++)
                #pragma unroll
                for (int nf = 0; nf < 4; nf++)
                    mma8(d[mf][nf], a[mf], b[nf]);
        }

        #pragma unroll
        for (int mf = 0; mf < 2; mf++) {
            #pragma unroll
            for (int half = 0; half < 2; half++) {
                int m = m0 + wm * 32 + mf * 16 + half * 8 + grp;
                if (m < M) {
                    #pragma unroll
                    for (int nf = 0; nf < 4; nf++) {
                        int ncol = wn * 32 + nf * 8 + tg * 2;
                        float2 v;
                        v.x = d[mf][nf][half * 2 + 0] + bias2[ncol];
                        v.y = d[mf][nf][half * 2 + 1] + bias2[ncol + 1];
                        *reinterpret_cast<float2*>(&out[(size_t)m * COUT + ncol]) = v;
                    }
                }
            }
        }
    }
}

// ---------------- launch ----------------
extern "C" void kernel_launch(void* const* d_in, const int* in_sizes, int n_in,
                              void* d_out, int out_size) {
    const float* x       = (const float*)d_in[0];
    const int*   ei      = (const int*)d_in[1];
    const float* ew      = (const float*)d_in[2];
    const float* w1      = (const float*)d_in[3];
    const float* b1      = (const float*)d_in[4];
    const float* bn1_g   = (const float*)d_in[5];
    const float* bn1_b   = (const float*)d_in[6];
    const float* bn1_m   = (const float*)d_in[7];
    const float* bn1_v   = (const float*)d_in[8];
    const float* conv_ws = (const float*)d_in[9];
    const float* conv_bs = (const float*)d_in[10];
    const float* bns_g   = (const float*)d_in[11];
    const float* bns_b   = (const float*)d_in[12];
    const float* bns_m   = (const float*)d_in[13];
    const float* bns_v   = (const float*)d_in[14];
    const float* lin1_w  = (const float*)d_in[15];
    const float* lin1_b  = (const float*)d_in[16];
    const float* lin2_w  = (const float*)d_in[17];
    const float* lin2_b  = (const float*)d_in[18];

    int n = in_sizes[0] / C;     // 50000
    int e = in_sizes[2];         // 800000
    const int* srcp = ei;
    const int* dstp = ei + e;

    const int SMEM_GEMM = 256 * APITCH * 4;   // 135168
    const int SMEM_HEAD = 320 * APITCH * 4;   // 168960

    cudaFuncSetAttribute(gemm_bn_kernel<0>, cudaFuncAttributeMaxDynamicSharedMemorySize, SMEM_GEMM);
    cudaFuncSetAttribute(gemm_bn_kernel<1>, cudaFuncAttributeMaxDynamicSharedMemorySize, SMEM_GEMM);
    cudaFuncSetAttribute(head_kernel,       cudaFuncAttributeMaxDynamicSharedMemorySize, SMEM_HEAD);

    float* wt = nullptr;   cudaGetSymbolAddress((void**)&wt, g_wt);
    float* bufA = nullptr; cudaGetSymbolAddress((void**)&bufA, g_bufA);
    float* bufB = nullptr; cudaGetSymbolAddress((void**)&bufB, g_bufB);

    int nb_e = (e + 255) / 256;
    count_tr_kernel<<<nb_e + (5 * 16384 - 8192 + 255) / 256, 256>>>(dstp, ew, e, w1, conv_ws, lin1_w, lin2_w);
    scan_fused_kernel<<<1, 1024>>>(n, b1, bn1_g, bn1_b, bn1_m, bn1_v,
                                   conv_bs, bns_g, bns_b, bns_m, bns_v);
    fill_kernel<<<nb_e, 256>>>(srcp, dstp, ew, e);

    int ablocks = (n + 7) / 8;
    int gblocks = (n + 127) / 128;

    // layer 0: agg(x) -> g_agg ; bufA = lrelu(bn0(g_agg @ w1))    <- agg at ncu slot
    agg_kernel<<<ablocks, 256>>>(x, n);
    gemm_bn_kernel<0><<<gblocks, 256, SMEM_GEMM>>>(wt + 0 * 16384, 0, nullptr, bufA, n);

    // layer 1
    agg_kernel<<<ablocks, 256>>>(bufA, n);
    gemm_bn_kernel<1><<<gblocks, 256, SMEM_GEMM>>>(wt + 1 * 16384, 1, bufA, bufB, n);

    // layer 2
    agg_kernel<<<ablocks, 256>>>(bufB, n);
    gemm_bn_kernel<1><<<gblocks, 256, SMEM_GEMM>>>(wt + 2 * 16384, 2, bufB, bufA, n);

    // fused heads
    head_kernel<<<gblocks, 256, SMEM_HEAD>>>(bufA, wt + 3 * 16384, lin1_b, wt + 4 * 16384, lin2_b,
                                             (float*)d_out, n);

    zero_kernel<<<(n + 255) / 256, 256>>>(n);
}